// round 3
// baseline (speedup 1.0000x reference)
#include <cuda_runtime.h>
#include <math.h>

#define BB 64
#define NN 4096
#define KS 16
#define DI 256
#define DO 256
#define HI 512
#define TT 3
#define LN_EPS 1e-5f
#define NCH 64   // n-chunks for the big attention pass (64 rows per block)
#define SCH 32   // chunks for the LN0 stats pass

// ---------------- device scratch (static, no allocations) ----------------
__device__ float g_spartA[SCH * BB];
__device__ float g_spartB[SCH * BB];
__device__ float g_mean[BB];
__device__ float g_rstd[BB];
__device__ float g_slots[BB * KS * DO];
__device__ float g_q[BB * KS * DO];
__device__ float g_qk[BB * KS * DI];
__device__ float g_qkb[BB * KS];
__device__ float g_upart[(size_t)NCH * BB * KS * DI];   // 67 MB partials
__device__ float g_Spart[NCH * BB * KS];
__device__ float g_spre[BB * KS * DO];

// ---------------- LN0 statistics: per-batch mean/var over N*DIN ----------
__global__ void __launch_bounds__(256) k_stats(const float* __restrict__ in) {
    int b = blockIdx.x, c = blockIdx.y, tid = threadIdx.x;
    const float4* p = (const float4*)(in + (size_t)b * NN * DI);
    const int per = (NN * DI / 4) / SCH;  // 8192 float4 per chunk
    float s = 0.f, s2 = 0.f;
    for (int i = tid; i < per; i += 256) {
        float4 v = p[(size_t)c * per + i];
        s  += v.x + v.y + v.z + v.w;
        s2 += v.x * v.x + v.y * v.y + v.z * v.z + v.w * v.w;
    }
    __shared__ float r1[256], r2[256];
    r1[tid] = s; r2[tid] = s2; __syncthreads();
    for (int o = 128; o > 0; o >>= 1) {
        if (tid < o) { r1[tid] += r1[tid + o]; r2[tid] += r2[tid + o]; }
        __syncthreads();
    }
    if (tid == 0) { g_spartA[c * BB + b] = r1[0]; g_spartB[c * BB + b] = r2[0]; }
}

__global__ void k_fin() {
    int b = threadIdx.x;
    if (b >= BB) return;
    float s = 0.f, s2 = 0.f;
    for (int c = 0; c < SCH; c++) { s += g_spartA[c * BB + b]; s2 += g_spartB[c * BB + b]; }
    const float inv = 1.0f / (float)(NN * DI);
    float m = s * inv;
    float v = s2 * inv - m * m;
    g_mean[b] = m;
    g_rstd[b] = rsqrtf(v + LN_EPS);
}

// ---------------- slots = mu + exp(logsigma) * slots_init ---------------
__global__ void k_sinit(const float* __restrict__ si, const float* __restrict__ mu,
                        const float* __restrict__ ls) {
    int i = blockIdx.x * 256 + threadIdx.x;
    int d = i & (DO - 1);
    g_slots[i] = mu[d] + expf(ls[d]) * si[i];
}

// ---------------- LN1(slots) -> q = s @ qW^T + qb  (grid: BB x 2) -------
__global__ void __launch_bounds__(256) k_q(const float* __restrict__ ln1w,
                                           const float* __restrict__ ln1b,
                                           const float* __restrict__ qW,
                                           const float* __restrict__ qb, int t) {
    int b = blockIdx.x, kh = blockIdx.y, tid = threadIdx.x;
    __shared__ float sl[KS * DO];     // raw slots (for stats)
    __shared__ float ss[8 * DO];      // normalized s for our 8 slots
    __shared__ float r1[256], r2[256];
    float s = 0.f, s2 = 0.f;
    for (int i = tid; i < KS * DO; i += 256) {
        float v = g_slots[b * KS * DO + i];
        sl[i] = v; s += v; s2 += v * v;
    }
    r1[tid] = s; r2[tid] = s2; __syncthreads();
    for (int o = 128; o > 0; o >>= 1) {
        if (tid < o) { r1[tid] += r1[tid + o]; r2[tid] += r2[tid + o]; }
        __syncthreads();
    }
    const float invC = 1.0f / (float)(KS * DO);
    float m = r1[0] * invC;
    float rs = rsqrtf(r2[0] * invC - m * m + LN_EPS);
    for (int i = tid; i < 8 * DO; i += 256) {
        int gi = kh * 8 * DO + i;
        ss[i] = (sl[gi] - m) * rs * ln1w[gi] + ln1b[gi];
    }
    __syncthreads();

    float acc[8] = {0.f, 0.f, 0.f, 0.f, 0.f, 0.f, 0.f, 0.f};
    const float4* qr = (const float4*)(qW + (size_t)t * DO * DO + (size_t)tid * DO);
    const float4* s4 = (const float4*)ss;
    for (int d = 0; d < DO / 4; d++) {
        float4 wv = qr[d];
#pragma unroll
        for (int k = 0; k < 8; k++) {
            float4 sv = s4[k * (DO / 4) + d];
            acc[k] += wv.x * sv.x + wv.y * sv.y + wv.z * sv.z + wv.w * sv.w;
        }
    }
    float qbv = qb[t * DO + tid];
#pragma unroll
    for (int k = 0; k < 8; k++)
        g_q[b * KS * DO + (kh * 8 + k) * DO + tid] = acc[k] + qbv;
}

// ---------------- qk = q @ kW (contract e), qkb = q . kb  (grid: BB x 2) -
__global__ void __launch_bounds__(256) k_qk(const float* __restrict__ kW,
                                            const float* __restrict__ kb, int t) {
    int b = blockIdx.x, kh = blockIdx.y, tid = threadIdx.x;
    __shared__ float qs[8 * DO];
    for (int i = tid; i < 8 * DO; i += 256)
        qs[i] = g_q[b * KS * DO + kh * 8 * DO + i];
    __syncthreads();
    const float* kWt = kW + (size_t)t * DO * DI;
    float acc[8] = {0.f, 0.f, 0.f, 0.f, 0.f, 0.f, 0.f, 0.f};
    for (int e = 0; e < DO; e++) {
        float kv = kWt[(size_t)e * DI + tid];   // coalesced
#pragma unroll
        for (int k = 0; k < 8; k++) acc[k] += qs[k * DO + e] * kv;
    }
#pragma unroll
    for (int k = 0; k < 8; k++)
        g_qk[b * KS * DI + (kh * 8 + k) * DI + tid] = acc[k];
    if (tid < 8) {
        float sb = 0.f;
        for (int e = 0; e < DO; e++) sb += qs[tid * DO + e] * kb[t * DO + e];
        g_qkb[b * KS + kh * 8 + tid] = sb;
    }
}

// ---------------- the big fused attention pass  (grid: BB x NCH) --------
// Per block: 64 rows of x (LN0 applied on the fly). For each 16-row tile:
//   phase1: dist[k][n] = (qk[k] . x[n] + qkb[k]) / 16
//   softmax over slot dim, then accumulate u[k][d] += attn * x[n][d] in regs.
__global__ void __launch_bounds__(256) k_attn(const float* __restrict__ in,
                                              const float* __restrict__ ln0w,
                                              const float* __restrict__ ln0b) {
    int b = blockIdx.x, ch = blockIdx.y, tid = threadIdx.x;
    __shared__ float4 qks[KS * (DI / 4)];  // 16 KB (prescaled by 1/16)
    __shared__ float  qkbs[KS];
    __shared__ float4 xs[16 * 65];         // 16 rows, padded stride (16.6 KB)
    __shared__ float  dist[KS][17];
    __shared__ float  attn[KS][17];

    const float4* gq = (const float4*)(g_qk + (size_t)b * KS * DI);
    const float isc = 1.0f / (float)KS;
    for (int i = tid; i < KS * (DI / 4); i += 256) {
        float4 v = gq[i];
        v.x *= isc; v.y *= isc; v.z *= isc; v.w *= isc;
        qks[i] = v;
    }
    if (tid < KS) qkbs[tid] = g_qkb[b * KS + tid] * isc;
    float mean = g_mean[b], rstd = g_rstd[b];

    int kp = tid >> 4, lo = tid & 15;
    float4 u0 = make_float4(0.f, 0.f, 0.f, 0.f), u1 = u0, u2 = u0, u3 = u0;
    float Sa = 0.f;
    __syncthreads();

    for (int g = 0; g < 4; g++) {
        int n0 = ch * 64 + g * 16;
        const float4* xin = (const float4*)(in + ((size_t)b * NN + n0) * DI);
        const float4* wv4 = (const float4*)(ln0w + (size_t)n0 * DI);
        const float4* bv4 = (const float4*)(ln0b + (size_t)n0 * DI);
        for (int i = tid; i < 1024; i += 256) {
            int row = i >> 6, c = i & 63;
            float4 v = xin[i];
            float4 w = wv4[i];
            float4 bb = bv4[i];
            float4 o;
            o.x = (v.x - mean) * rstd * w.x + bb.x;
            o.y = (v.y - mean) * rstd * w.y + bb.y;
            o.z = (v.z - mean) * rstd * w.z + bb.z;
            o.w = (v.w - mean) * rstd * w.w + bb.w;
            xs[row * 65 + c] = o;
        }
        __syncthreads();

        // phase1: thread (kp, lo=row): dot over 256
        {
            float a = 0.f;
            const float4* xr = &xs[lo * 65];
            const float4* qr = &qks[kp * 64];
#pragma unroll 8
            for (int d = 0; d < 64; d++) {
                float4 q4 = qr[d], x4 = xr[d];
                a += q4.x * x4.x + q4.y * x4.y + q4.z * x4.z + q4.w * x4.w;
            }
            dist[kp][lo] = a + qkbs[kp];
        }
        __syncthreads();

        // softmax over slot dim, per row
        if (tid < 16) {
            float mx = -1e30f;
#pragma unroll
            for (int k = 0; k < KS; k++) mx = fmaxf(mx, dist[k][tid]);
            float sm = 0.f;
#pragma unroll
            for (int k = 0; k < KS; k++) {
                float e = __expf(dist[k][tid] - mx);
                attn[k][tid] = e; sm += e;
            }
            float iv = 1.0f / sm;
#pragma unroll
            for (int k = 0; k < KS; k++) attn[k][tid] *= iv;
        }
        __syncthreads();

        if (tid < 16) {
#pragma unroll
            for (int n = 0; n < 16; n++) Sa += attn[tid][n];
        }

        // phase2: thread (kp, lo=d-group): u[kp][lo*16 .. +15] accumulation
#pragma unroll 4
        for (int n = 0; n < 16; n++) {
            float w = attn[kp][n];
            const float4* xp = &xs[n * 65 + lo * 4];
            float4 a0 = xp[0], a1 = xp[1], a2 = xp[2], a3 = xp[3];
            u0.x += w * a0.x; u0.y += w * a0.y; u0.z += w * a0.z; u0.w += w * a0.w;
            u1.x += w * a1.x; u1.y += w * a1.y; u1.z += w * a1.z; u1.w += w * a1.w;
            u2.x += w * a2.x; u2.y += w * a2.y; u2.z += w * a2.z; u2.w += w * a2.w;
            u3.x += w * a3.x; u3.y += w * a3.y; u3.z += w * a3.z; u3.w += w * a3.w;
        }
        __syncthreads();
    }

    float4* up = (float4*)(g_upart + ((size_t)ch * BB + b) * KS * DI + kp * DI + lo * 16);
    up[0] = u0; up[1] = u1; up[2] = u2; up[3] = u3;
    if (tid < 16) g_Spart[(ch * BB + b) * KS + tid] = Sa;
}

// ---------------- reduce partials, wx = u/(S+eps), V proj  (grid: BB x 2)
__global__ void __launch_bounds__(256) k_vproj(const float* __restrict__ vW,
                                               const float* __restrict__ vb, int t) {
    int b = blockIdx.x, kh = blockIdx.y, tid = threadIdx.x;
    __shared__ float wxs[8 * DI];
    __shared__ float wss[8], ivs[8];
    if (tid < 8) {
        float S = 0.f;
        for (int c = 0; c < NCH; c++) S += g_Spart[(c * BB + b) * KS + kh * 8 + tid];
        float iv = 1.0f / (S + 1e-7f);
        ivs[tid] = iv; wss[tid] = S * iv;
    }
    __syncthreads();
    for (int i = tid; i < 8 * DI; i += 256) {
        int k = i >> 8;
        size_t base = (size_t)b * KS * DI + (size_t)(kh * 8 + k) * DI + (i & 255);
        float s = 0.f;
#pragma unroll 8
        for (int c = 0; c < NCH; c++) s += g_upart[(size_t)c * BB * KS * DI + base];
        wxs[i] = s * ivs[k];
    }
    __syncthreads();
    const float4* vr = (const float4*)(vW + (size_t)t * DO * DI + (size_t)tid * DI);
    const float4* w4 = (const float4*)wxs;
    float acc[8] = {0.f, 0.f, 0.f, 0.f, 0.f, 0.f, 0.f, 0.f};
    for (int d = 0; d < DI / 4; d++) {
        float4 wv = vr[d];
#pragma unroll
        for (int k = 0; k < 8; k++) {
            float4 xv = w4[k * (DI / 4) + d];
            acc[k] += wv.x * xv.x + wv.y * xv.y + wv.z * xv.z + wv.w * xv.w;
        }
    }
    float vbv = vb[t * DO + tid];
#pragma unroll
    for (int k = 0; k < 8; k++)
        g_spre[b * KS * DO + (kh * 8 + k) * DO + tid] = acc[k] + vbv * wss[k];
}

// ---------------- LN2 + MLP + residual  (grid: BB x 4, 4 slots/block) ---
__global__ void __launch_bounds__(256) k_mlp(const float* __restrict__ ln2w,
                                             const float* __restrict__ ln2b,
                                             const float* __restrict__ m1W,
                                             const float* __restrict__ m1b,
                                             const float* __restrict__ m2W,
                                             const float* __restrict__ m2b,
                                             int t, float* __restrict__ out) {
    int b = blockIdx.x, kq = blockIdx.y, tid = threadIdx.x;
    __shared__ float h0[4 * DO];
    __shared__ float hh[4 * HI];
    __shared__ float r1[256], r2[256];
    float s = 0.f, s2 = 0.f;
    for (int i = tid; i < KS * DO; i += 256) {
        float v = g_spre[b * KS * DO + i];
        s += v; s2 += v * v;
    }
    r1[tid] = s; r2[tid] = s2; __syncthreads();
    for (int o = 128; o > 0; o >>= 1) {
        if (tid < o) { r1[tid] += r1[tid + o]; r2[tid] += r2[tid + o]; }
        __syncthreads();
    }
    const float invC = 1.0f / (float)(KS * DO);
    float m = r1[0] * invC;
    float rs = rsqrtf(r2[0] * invC - m * m + LN_EPS);
    for (int i = tid; i < 4 * DO; i += 256) {
        int gi = kq * 4 * DO + i;
        float v = g_spre[b * KS * DO + gi];
        h0[i] = (v - m) * rs * ln2w[gi] + ln2b[gi];
    }
    __syncthreads();

    const float* m1 = m1W + (size_t)t * HI * DO;
    const float4* h04 = (const float4*)h0;
    for (int jj = tid; jj < HI; jj += 256) {
        const float4* mr = (const float4*)(m1 + (size_t)jj * DO);
        float a[4] = {0.f, 0.f, 0.f, 0.f};
        for (int d = 0; d < DO / 4; d++) {
            float4 wv = mr[d];
#pragma unroll
            for (int k = 0; k < 4; k++) {
                float4 hv = h04[k * (DO / 4) + d];
                a[k] += wv.x * hv.x + wv.y * hv.y + wv.z * hv.z + wv.w * hv.w;
            }
        }
        float bb = m1b[t * HI + jj];
#pragma unroll
        for (int k = 0; k < 4; k++) hh[k * HI + jj] = fmaxf(a[k] + bb, 0.0f);
    }
    __syncthreads();

    const float4* m2r = (const float4*)(m2W + (size_t)t * DO * HI + (size_t)tid * HI);
    const float4* hh4 = (const float4*)hh;
    float a[4] = {0.f, 0.f, 0.f, 0.f};
    for (int j = 0; j < HI / 4; j++) {
        float4 wv = m2r[j];
#pragma unroll
        for (int k = 0; k < 4; k++) {
            float4 hv = hh4[k * (HI / 4) + j];
            a[k] += wv.x * hv.x + wv.y * hv.y + wv.z * hv.z + wv.w * hv.w;
        }
    }
    float b2 = m2b[t * DO + tid];
#pragma unroll
    for (int k = 0; k < 4; k++) {
        int gi = (kq * 4 + k) * DO + tid;
        float val = g_spre[b * KS * DO + gi] + a[k] + b2;
        g_slots[b * KS * DO + gi] = val;         // feeds next iteration
        if (out) out[(size_t)b * KS * DO + gi] = val;  // final output
    }
}

// ---------------- host launcher -----------------------------------------
extern "C" void kernel_launch(void* const* d_in, const int* in_sizes, int n_in,
                              void* d_out, int out_size) {
    const float* inputs     = (const float*)d_in[0];
    const float* slots_init = (const float*)d_in[1];
    const float* mu         = (const float*)d_in[2];
    const float* logsigma   = (const float*)d_in[3];
    const float* ln0w       = (const float*)d_in[4];
    const float* ln0b       = (const float*)d_in[5];
    const float* ln1w       = (const float*)d_in[6];
    const float* ln1b       = (const float*)d_in[7];
    const float* ln2w       = (const float*)d_in[8];
    const float* ln2b       = (const float*)d_in[9];
    const float* qW         = (const float*)d_in[10];
    const float* qb         = (const float*)d_in[11];
    const float* kW         = (const float*)d_in[12];
    const float* kb         = (const float*)d_in[13];
    const float* vW         = (const float*)d_in[14];
    const float* vb         = (const float*)d_in[15];
    const float* m1W        = (const float*)d_in[16];
    const float* m1b        = (const float*)d_in[17];
    const float* m2W        = (const float*)d_in[18];
    const float* m2b        = (const float*)d_in[19];
    float* out = (float*)d_out;

    k_stats<<<dim3(BB, SCH), 256>>>(inputs);
    k_fin<<<1, BB>>>();
    k_sinit<<<(BB * KS * DO) / 256, 256>>>(slots_init, mu, logsigma);

    for (int t = 0; t < TT; t++) {
        k_q<<<dim3(BB, 2), 256>>>(ln1w, ln1b, qW, qb, t);
        k_qk<<<dim3(BB, 2), 256>>>(kW, kb, t);
        k_attn<<<dim3(BB, NCH), 256>>>(inputs, ln0w, ln0b);
        k_vproj<<<dim3(BB, 2), 256>>>(vW, vb, t);
        k_mlp<<<dim3(BB, 4), 256>>>(ln2w, ln2b, m1W, m1b, m2W, m2b, t,
                                    (t == TT - 1) ? out : (float*)nullptr);
    }
}

// round 4
// speedup vs baseline: 2.4995x; 2.4995x over previous
#include <cuda_runtime.h>
#include <math.h>

#define BB 64
#define NN 4096
#define KS 16
#define DI 256
#define DO 256
#define HI 512
#define TT 3
#define LN_EPS 1e-5f
#define NCH 64   // n-chunks for the big attention pass (64 rows per block)
#define SCH 32   // chunks for the LN0 stats pass

// ---------------- device scratch (static, no allocations) ----------------
__device__ float g_spartA[SCH * BB];
__device__ float g_spartB[SCH * BB];
__device__ float g_mean[BB];
__device__ float g_rstd[BB];
__device__ float g_slots[BB * KS * DO];
__device__ float g_qk[BB * KS * DI];     // PRE-scaled by 1/KS
__device__ float g_qkb[BB * KS];         // PRE-scaled by 1/KS
__device__ float g_upart[(size_t)NCH * BB * KS * DI];
__device__ float g_Spart[NCH * BB * KS];
__device__ float g_spre[BB * KS * DO];
// folded / transposed weights
__device__ float g_Wqk[DO * DI];         // Wqk[d][i] = sum_e qW[e][d] kW[e][i]
__device__ float g_wqb[DI];              // sum_e qb[e] kW[e][i]
__device__ float g_wb[DO];               // sum_e qW[e][d] kb[e]
__device__ float g_c0[1];                // qb . kb
__device__ float g_vWt[TT * DI * DO];    // vWt[t][d][e]
__device__ float g_m1Wt[TT * DO * HI];   // m1Wt[t][d][j]
__device__ float g_m2Wt[TT * HI * DO];   // m2Wt[t][h][e]

// ---------------- generic 32x32 tiled transpose (rows R, cols C) --------
__global__ void __launch_bounds__(256) k_tr(const float* __restrict__ src,
                                            float* __restrict__ dst, int R, int C) {
    __shared__ float tile[32][33];
    int z = blockIdx.z;
    const float* s = src + (size_t)z * R * C;
    float* d = dst + (size_t)z * R * C;
    int c0 = blockIdx.x * 32, r0 = blockIdx.y * 32;
    int x = threadIdx.x & 31, y = threadIdx.x >> 5;  // 32 x 8
    for (int yy = y; yy < 32; yy += 8)
        tile[yy][x] = s[(size_t)(r0 + yy) * C + c0 + x];
    __syncthreads();
    for (int yy = y; yy < 32; yy += 8)
        d[(size_t)(c0 + yy) * R + r0 + x] = tile[x][yy];
}

// ---------------- LN0 statistics ----------------------------------------
__global__ void __launch_bounds__(256) k_stats(const float* __restrict__ in) {
    int b = blockIdx.x, c = blockIdx.y, tid = threadIdx.x;
    const float4* p = (const float4*)(in + (size_t)b * NN * DI);
    const int per = (NN * DI / 4) / SCH;
    float s = 0.f, s2 = 0.f;
    for (int i = tid; i < per; i += 256) {
        float4 v = p[(size_t)c * per + i];
        s  += v.x + v.y + v.z + v.w;
        s2 += v.x * v.x + v.y * v.y + v.z * v.z + v.w * v.w;
    }
    __shared__ float r1[256], r2[256];
    r1[tid] = s; r2[tid] = s2; __syncthreads();
    for (int o = 128; o > 0; o >>= 1) {
        if (tid < o) { r1[tid] += r1[tid + o]; r2[tid] += r2[tid + o]; }
        __syncthreads();
    }
    if (tid == 0) { g_spartA[c * BB + b] = r1[0]; g_spartB[c * BB + b] = r2[0]; }
}

__global__ void k_fin() {
    int b = threadIdx.x;
    if (b >= BB) return;
    float s = 0.f, s2 = 0.f;
    for (int c = 0; c < SCH; c++) { s += g_spartA[c * BB + b]; s2 += g_spartB[c * BB + b]; }
    const float inv = 1.0f / (float)(NN * DI);
    float m = s * inv;
    float v = s2 * inv - m * m;
    g_mean[b] = m;
    g_rstd[b] = rsqrtf(v + LN_EPS);
}

// ---------------- slots = mu + exp(logsigma) * slots_init ---------------
__global__ void k_sinit(const float* __restrict__ si, const float* __restrict__ mu,
                        const float* __restrict__ ls) {
    int i = blockIdx.x * 256 + threadIdx.x;
    int d = i & (DO - 1);
    g_slots[i] = mu[d] + expf(ls[d]) * si[i];
}

// ---------------- Wqk = qW^T @ kW  (grid: 64 blocks, 4 d per block) -----
__global__ void __launch_bounds__(256) k_wqk(const float* __restrict__ qW,
                                             const float* __restrict__ qb,
                                             const float* __restrict__ kW,
                                             const float* __restrict__ kb, int t) {
    int d0 = blockIdx.x * 4, i = threadIdx.x;
    __shared__ float qcols[DO * 4];
    __shared__ float kb_s[DO], qb_s[DO];
    {
        float4 v = *(const float4*)(qW + (size_t)t * DO * DO + (size_t)i * DO + d0);
        qcols[i * 4 + 0] = v.x; qcols[i * 4 + 1] = v.y;
        qcols[i * 4 + 2] = v.z; qcols[i * 4 + 3] = v.w;
        kb_s[i] = kb[t * DO + i];
        qb_s[i] = qb[t * DO + i];
    }
    __syncthreads();
    const float* kWt = kW + (size_t)t * DO * DI;
    float acc0 = 0.f, acc1 = 0.f, acc2 = 0.f, acc3 = 0.f, accq = 0.f;
    for (int e = 0; e < DO; e++) {
        float kv = kWt[(size_t)e * DI + i];
        acc0 += qcols[e * 4 + 0] * kv;
        acc1 += qcols[e * 4 + 1] * kv;
        acc2 += qcols[e * 4 + 2] * kv;
        acc3 += qcols[e * 4 + 3] * kv;
        accq += qb_s[e] * kv;
    }
    g_Wqk[(d0 + 0) * DI + i] = acc0;
    g_Wqk[(d0 + 1) * DI + i] = acc1;
    g_Wqk[(d0 + 2) * DI + i] = acc2;
    g_Wqk[(d0 + 3) * DI + i] = acc3;
    if (blockIdx.x == 0) g_wqb[i] = accq;
    if (i < 4) {
        float s = 0.f;
        for (int e = 0; e < DO; e++) s += qcols[e * 4 + i] * kb_s[e];
        g_wb[d0 + i] = s;
    }
    if (blockIdx.x == 0 && i == 0) {
        float s = 0.f;
        for (int e = 0; e < DO; e++) s += qb_s[e] * kb_s[e];
        g_c0[0] = s;
    }
}

// ---------------- LN1(slots) -> qk = sn @ Wqk + wqb  (grid: BB x 2) -----
__global__ void __launch_bounds__(256) k_qk(const float* __restrict__ ln1w,
                                            const float* __restrict__ ln1b) {
    int b = blockIdx.x, kh = blockIdx.y, tid = threadIdx.x;
    __shared__ float sl[KS * DO];
    __shared__ float ss[8 * DO];
    __shared__ float r1[256], r2[256];
    float s = 0.f, s2 = 0.f;
    for (int i = tid; i < KS * DO; i += 256) {
        float v = g_slots[b * KS * DO + i];
        sl[i] = v; s += v; s2 += v * v;
    }
    r1[tid] = s; r2[tid] = s2; __syncthreads();
    for (int o = 128; o > 0; o >>= 1) {
        if (tid < o) { r1[tid] += r1[tid + o]; r2[tid] += r2[tid + o]; }
        __syncthreads();
    }
    const float invC = 1.0f / (float)(KS * DO);
    float m = r1[0] * invC;
    float rs = rsqrtf(r2[0] * invC - m * m + LN_EPS);
    for (int i = tid; i < 8 * DO; i += 256) {
        int gi = kh * 8 * DO + i;
        ss[i] = (sl[gi] - m) * rs * ln1w[gi] + ln1b[gi];
    }
    __syncthreads();

    const float isc = 1.0f / (float)KS;
    float acc[8] = {0.f, 0.f, 0.f, 0.f, 0.f, 0.f, 0.f, 0.f};
    for (int d = 0; d < DO; d++) {
        float wv = g_Wqk[d * DI + tid];   // coalesced
#pragma unroll
        for (int k = 0; k < 8; k++) acc[k] += ss[k * DO + d] * wv;
    }
    float wqbv = g_wqb[tid];
#pragma unroll
    for (int k = 0; k < 8; k++)
        g_qk[b * KS * DI + (kh * 8 + k) * DI + tid] = (acc[k] + wqbv) * isc;
    if (tid < 8) {
        float sb = 0.f;
        for (int d = 0; d < DO; d++) sb += ss[tid * DO + d] * g_wb[d];
        g_qkb[b * KS + kh * 8 + tid] = (sb + g_c0[0]) * isc;
    }
}

// ---------------- the big fused attention pass  (grid: BB x NCH) --------
// Thread mapping (both phases): kk = tid&15 (slot), dg = tid>>4 (16-d group).
// qk row segment lives in registers; all x reads are smem broadcasts.
__global__ void __launch_bounds__(256, 2) k_attn(const float* __restrict__ in,
                                                 const float* __restrict__ ln0w,
                                                 const float* __restrict__ ln0b) {
    int b = blockIdx.x, ch = blockIdx.y, tid = threadIdx.x;
    int kk = tid & 15, dg = tid >> 4;
    int wid = tid >> 5, lane = tid & 31;

    __shared__ float4 xs[16 * 64];       // 16 rows x 256 floats, 16 KB
    __shared__ float  dist[KS][17];
    __shared__ float  attn[KS][17];
    __shared__ float  red[8][16 * 17];   // per-warp partials, padded
    __shared__ float  qkb_s[KS];

    // qk segment for (kk, dg): 16 floats in registers (already /KS scaled)
    const float4* qp = (const float4*)(g_qk + ((size_t)b * KS + kk) * DI + dg * 16);
    float4 q0 = qp[0], q1 = qp[1], q2 = qp[2], q3 = qp[3];
    if (tid < KS) qkb_s[tid] = g_qkb[b * KS + tid];
    float mean = g_mean[b], rstd = g_rstd[b];

    float4 u0 = make_float4(0.f, 0.f, 0.f, 0.f), u1 = u0, u2 = u0, u3 = u0;
    float Sa = 0.f;
    __syncthreads();

    for (int g = 0; g < 4; g++) {
        int n0 = ch * 64 + g * 16;
        const float4* xin = (const float4*)(in + ((size_t)b * NN + n0) * DI);
        const float4* wv4 = (const float4*)(ln0w + (size_t)n0 * DI);
        const float4* bv4 = (const float4*)(ln0b + (size_t)n0 * DI);
        for (int i = tid; i < 1024; i += 256) {
            float4 v = xin[i], w = wv4[i], bb = bv4[i];
            float4 o;
            o.x = (v.x - mean) * rstd * w.x + bb.x;
            o.y = (v.y - mean) * rstd * w.y + bb.y;
            o.z = (v.z - mean) * rstd * w.z + bb.z;
            o.w = (v.w - mean) * rstd * w.w + bb.w;
            xs[i] = o;
        }
        __syncthreads();

        // phase1: partial dots over this thread's 16-d segment, all 16 n
        float p[16];
#pragma unroll
        for (int n = 0; n < 16; n++) {
            const float4* xr = &xs[n * 64 + dg * 4];
            float4 a0 = xr[0], a1 = xr[1], a2 = xr[2], a3 = xr[3];
            float s;
            s  = q0.x * a0.x + q0.y * a0.y + q0.z * a0.z + q0.w * a0.w;
            s += q1.x * a1.x + q1.y * a1.y + q1.z * a1.z + q1.w * a1.w;
            s += q2.x * a2.x + q2.y * a2.y + q2.z * a2.z + q2.w * a2.w;
            s += q3.x * a3.x + q3.y * a3.y + q3.z * a3.z + q3.w * a3.w;
            p[n] = s;
        }
        // fold dg pairs within warp (lanes differ in bit4 => same kk)
#pragma unroll
        for (int n = 0; n < 16; n++)
            p[n] += __shfl_xor_sync(0xffffffffu, p[n], 16);
        if (lane < 16) {
#pragma unroll
            for (int n = 0; n < 16; n++) red[wid][lane * 17 + n] = p[n];
        }
        __syncthreads();

        // reduce 8 warps -> dist
        {
            int rkk = tid & 15, rn = tid >> 4;
            float s = 0.f;
#pragma unroll
            for (int w = 0; w < 8; w++) s += red[w][rkk * 17 + rn];
            dist[rkk][rn] = s + qkb_s[rkk];
        }
        __syncthreads();

        // softmax over slot dim, per row n = tid
        if (tid < 16) {
            float mx = -1e30f;
#pragma unroll
            for (int k = 0; k < KS; k++) mx = fmaxf(mx, dist[k][tid]);
            float sm = 0.f;
#pragma unroll
            for (int k = 0; k < KS; k++) {
                float e = __expf(dist[k][tid] - mx);
                attn[k][tid] = e; sm += e;
            }
            float iv = 1.0f / sm;
#pragma unroll
            for (int k = 0; k < KS; k++) attn[k][tid] *= iv;
        }
        __syncthreads();

        if (tid < 16) {
#pragma unroll
            for (int n = 0; n < 16; n++) Sa += attn[tid][n];
        }

        // phase2: u[kk][dg*16..+15] += attn[kk][n] * x[n][...]  (broadcast x)
#pragma unroll
        for (int n = 0; n < 16; n++) {
            float w = attn[kk][n];
            const float4* xr = &xs[n * 64 + dg * 4];
            float4 a0 = xr[0], a1 = xr[1], a2 = xr[2], a3 = xr[3];
            u0.x += w * a0.x; u0.y += w * a0.y; u0.z += w * a0.z; u0.w += w * a0.w;
            u1.x += w * a1.x; u1.y += w * a1.y; u1.z += w * a1.z; u1.w += w * a1.w;
            u2.x += w * a2.x; u2.y += w * a2.y; u2.z += w * a2.z; u2.w += w * a2.w;
            u3.x += w * a3.x; u3.y += w * a3.y; u3.z += w * a3.z; u3.w += w * a3.w;
        }
        __syncthreads();
    }

    float4* up = (float4*)(g_upart + (((size_t)ch * BB + b) * KS + kk) * DI + dg * 16);
    up[0] = u0; up[1] = u1; up[2] = u2; up[3] = u3;
    if (tid < 16) g_Spart[(ch * BB + b) * KS + tid] = Sa;
}

// ---------------- reduce partials, V proj (transposed vW)  (grid: BB x 2)
__global__ void __launch_bounds__(256) k_vproj(const float* __restrict__ vb, int t) {
    int b = blockIdx.x, kh = blockIdx.y, tid = threadIdx.x;
    __shared__ float wxs[8 * DI];
    __shared__ float wss[8], ivs[8];
    if (tid < 8) {
        float S = 0.f;
        for (int c = 0; c < NCH; c++) S += g_Spart[(c * BB + b) * KS + kh * 8 + tid];
        float iv = 1.0f / (S + 1e-7f);
        ivs[tid] = iv; wss[tid] = S * iv;
    }
    __syncthreads();
    // 8 k * 64 float4 = 512 float4; each thread reduces 2 over 64 chunks
    for (int ii = tid; ii < 512; ii += 256) {
        int k = ii >> 6;
        const float4* src = (const float4*)g_upart +
            (((size_t)b * KS) + kh * 8 + k) * (DI / 4) + (ii & 63);
        float4 s = make_float4(0.f, 0.f, 0.f, 0.f);
#pragma unroll 8
        for (int c = 0; c < NCH; c++) {
            float4 v = src[(size_t)c * (BB * KS * DI / 4)];
            s.x += v.x; s.y += v.y; s.z += v.z; s.w += v.w;
        }
        float iv = ivs[k];
        s.x *= iv; s.y *= iv; s.z *= iv; s.w *= iv;
        ((float4*)wxs)[ii] = s;
    }
    __syncthreads();
    const float* vt = g_vWt + (size_t)t * DI * DO;
    float acc[8] = {0.f, 0.f, 0.f, 0.f, 0.f, 0.f, 0.f, 0.f};
    for (int d = 0; d < DI; d++) {
        float wv = vt[(size_t)d * DO + tid];  // coalesced
#pragma unroll
        for (int k = 0; k < 8; k++) acc[k] += wxs[k * DI + d] * wv;
    }
    float vbv = vb[t * DO + tid];
#pragma unroll
    for (int k = 0; k < 8; k++)
        g_spre[b * KS * DO + (kh * 8 + k) * DO + tid] = acc[k] + vbv * wss[k];
}

// ---------------- LN2 + MLP + residual (transposed weights) -------------
__global__ void __launch_bounds__(256) k_mlp(const float* __restrict__ ln2w,
                                             const float* __restrict__ ln2b,
                                             const float* __restrict__ m1b,
                                             const float* __restrict__ m2b,
                                             int t, float* __restrict__ out) {
    int b = blockIdx.x, kq = blockIdx.y, tid = threadIdx.x;
    __shared__ float h0[4 * DO];
    __shared__ float hh[4 * HI];
    __shared__ float r1[256], r2[256];
    float s = 0.f, s2 = 0.f;
    for (int i = tid; i < KS * DO; i += 256) {
        float v = g_spre[b * KS * DO + i];
        s += v; s2 += v * v;
    }
    r1[tid] = s; r2[tid] = s2; __syncthreads();
    for (int o = 128; o > 0; o >>= 1) {
        if (tid < o) { r1[tid] += r1[tid + o]; r2[tid] += r2[tid + o]; }
        __syncthreads();
    }
    const float invC = 1.0f / (float)(KS * DO);
    float m = r1[0] * invC;
    float rs = rsqrtf(r2[0] * invC - m * m + LN_EPS);
    for (int i = tid; i < 4 * DO; i += 256) {
        int gi = kq * 4 * DO + i;
        float v = g_spre[b * KS * DO + gi];
        h0[i] = (v - m) * rs * ln2w[gi] + ln2b[gi];
    }
    __syncthreads();

    // GEMM1: hh[k][j] = relu( sum_d h0[k][d] * m1Wt[d][j] + m1b[j] )
    const float* w1 = g_m1Wt + (size_t)t * DO * HI;
    {
        float a0[4] = {0.f, 0.f, 0.f, 0.f}, a1[4] = {0.f, 0.f, 0.f, 0.f};
        for (int d = 0; d < DO; d++) {
            float wA = w1[(size_t)d * HI + tid];        // coalesced
            float wB = w1[(size_t)d * HI + tid + 256];  // coalesced
#pragma unroll
            for (int k = 0; k < 4; k++) {
                float hv = h0[k * DO + d];
                a0[k] += hv * wA; a1[k] += hv * wB;
            }
        }
        float bA = m1b[t * HI + tid], bB = m1b[t * HI + tid + 256];
#pragma unroll
        for (int k = 0; k < 4; k++) {
            hh[k * HI + tid]       = fmaxf(a0[k] + bA, 0.f);
            hh[k * HI + tid + 256] = fmaxf(a1[k] + bB, 0.f);
        }
    }
    __syncthreads();

    // GEMM2: out[k][e] = sum_h hh[k][h] * m2Wt[h][e]
    const float* w2 = g_m2Wt + (size_t)t * HI * DO;
    float a[4] = {0.f, 0.f, 0.f, 0.f};
    for (int h = 0; h < HI; h++) {
        float wv = w2[(size_t)h * DO + tid];  // coalesced
#pragma unroll
        for (int k = 0; k < 4; k++) a[k] += hh[k * HI + h] * wv;
    }
    float b2 = m2b[t * DO + tid];
#pragma unroll
    for (int k = 0; k < 4; k++) {
        int gi = (kq * 4 + k) * DO + tid;
        float val = g_spre[b * KS * DO + gi] + a[k] + b2;
        g_slots[b * KS * DO + gi] = val;
        if (out) out[(size_t)b * KS * DO + gi] = val;
    }
}

// ---------------- host launcher -----------------------------------------
extern "C" void kernel_launch(void* const* d_in, const int* in_sizes, int n_in,
                              void* d_out, int out_size) {
    const float* inputs     = (const float*)d_in[0];
    const float* slots_init = (const float*)d_in[1];
    const float* mu         = (const float*)d_in[2];
    const float* logsigma   = (const float*)d_in[3];
    const float* ln0w       = (const float*)d_in[4];
    const float* ln0b       = (const float*)d_in[5];
    const float* ln1w       = (const float*)d_in[6];
    const float* ln1b       = (const float*)d_in[7];
    const float* ln2w       = (const float*)d_in[8];
    const float* ln2b       = (const float*)d_in[9];
    const float* qW         = (const float*)d_in[10];
    const float* qb         = (const float*)d_in[11];
    const float* kW         = (const float*)d_in[12];
    const float* kb         = (const float*)d_in[13];
    const float* vW         = (const float*)d_in[14];
    const float* vb         = (const float*)d_in[15];
    const float* m1b        = (const float*)d_in[17];
    const float* m2b        = (const float*)d_in[19];
    const float* m1W        = (const float*)d_in[16];
    const float* m2W        = (const float*)d_in[18];
    float* out = (float*)d_out;

    // one-time prep (inside graph; cheap)
    float* vWt; cudaGetSymbolAddress((void**)&vWt, g_vWt);
    float* m1Wt; cudaGetSymbolAddress((void**)&m1Wt, g_m1Wt);
    float* m2Wt; cudaGetSymbolAddress((void**)&m2Wt, g_m2Wt);
    k_tr<<<dim3(DI / 32, DO / 32, TT), 256>>>(vW, vWt, DO, DI);    // [e][d]->[d][e]
    k_tr<<<dim3(DO / 32, HI / 32, TT), 256>>>(m1W, m1Wt, HI, DO);  // [h][d]->[d][h]
    k_tr<<<dim3(HI / 32, DO / 32, TT), 256>>>(m2W, m2Wt, DO, HI);  // [e][h]->[h][e]

    k_stats<<<dim3(BB, SCH), 256>>>(inputs);
    k_fin<<<1, BB>>>();
    k_sinit<<<(BB * KS * DO) / 256, 256>>>(slots_init, mu, logsigma);

    for (int t = 0; t < TT; t++) {
        k_wqk<<<64, 256>>>(qW, qb, kW, kb, t);
        k_qk<<<dim3(BB, 2), 256>>>(ln1w, ln1b);
        k_attn<<<dim3(BB, NCH), 256>>>(inputs, ln0w, ln0b);
        k_vproj<<<dim3(BB, 2), 256>>>(vb, t);
        k_mlp<<<dim3(BB, 4), 256>>>(ln2w, ln2b, m1b, m2b, t,
                                    (t == TT - 1) ? out : (float*)nullptr);
    }
}

// round 6
// speedup vs baseline: 2.7751x; 1.1103x over previous
#include <cuda_runtime.h>
#include <math.h>

#define BB 64
#define NN 4096
#define KS 16
#define DI 256
#define DO 256
#define HI 512
#define TT 3
#define LN_EPS 1e-5f
#define NCH 32   // n-chunks for the big attention pass (128 rows per block)
#define SCH 32   // chunks for the LN0 stats pass

// packed fp32x2 FMA (Blackwell FFMA2 — only reachable via PTX)
__device__ __forceinline__ void ffma2(float2& d, float2 a, float2 b) {
    asm("fma.rn.f32x2 %0, %1, %2, %0;"
        : "+l"(reinterpret_cast<unsigned long long&>(d))
        : "l"(reinterpret_cast<unsigned long long&>(a)),
          "l"(reinterpret_cast<unsigned long long&>(b)));
}

// ---------------- device scratch (static, no allocations) ----------------
__device__ float g_spartA[SCH * BB];
__device__ float g_spartB[SCH * BB];
__device__ float g_mean[BB];
__device__ float g_rstd[BB];
__device__ float g_slots[BB * KS * DO];
__device__ float g_qk[BB * KS * DI];     // PRE-scaled by 1/KS
__device__ float g_qkb[BB * KS];         // PRE-scaled by 1/KS
__device__ float g_upart[(size_t)NCH * BB * KS * DI];
__device__ float g_Spart[NCH * BB * KS];
__device__ float g_spre[BB * KS * DO];
// folded / transposed weights
__device__ float g_Wqk[DO * DI];
__device__ float g_wqb[DI];
__device__ float g_wb[DO];
__device__ float g_c0[1];
__device__ float g_vWt[TT * DI * DO];
__device__ float g_m1Wt[TT * DO * HI];
__device__ float g_m2Wt[TT * HI * DO];

// ---------------- generic 32x32 tiled transpose -------------------------
__global__ void __launch_bounds__(256) k_tr(const float* __restrict__ src,
                                            float* __restrict__ dst, int R, int C) {
    __shared__ float tile[32][33];
    int z = blockIdx.z;
    const float* s = src + (size_t)z * R * C;
    float* d = dst + (size_t)z * R * C;
    int c0 = blockIdx.x * 32, r0 = blockIdx.y * 32;
    int x = threadIdx.x & 31, y = threadIdx.x >> 5;
    for (int yy = y; yy < 32; yy += 8)
        tile[yy][x] = s[(size_t)(r0 + yy) * C + c0 + x];
    __syncthreads();
    for (int yy = y; yy < 32; yy += 8)
        d[(size_t)(c0 + yy) * R + r0 + x] = tile[x][yy];
}

// ---------------- LN0 statistics ----------------------------------------
__global__ void __launch_bounds__(256) k_stats(const float* __restrict__ in) {
    int b = blockIdx.x, c = blockIdx.y, tid = threadIdx.x;
    const float4* p = (const float4*)(in + (size_t)b * NN * DI);
    const int per = (NN * DI / 4) / SCH;
    float s = 0.f, s2 = 0.f;
    for (int i = tid; i < per; i += 256) {
        float4 v = p[(size_t)c * per + i];
        s  += v.x + v.y + v.z + v.w;
        s2 += v.x * v.x + v.y * v.y + v.z * v.z + v.w * v.w;
    }
    __shared__ float r1[256], r2[256];
    r1[tid] = s; r2[tid] = s2; __syncthreads();
    for (int o = 128; o > 0; o >>= 1) {
        if (tid < o) { r1[tid] += r1[tid + o]; r2[tid] += r2[tid + o]; }
        __syncthreads();
    }
    if (tid == 0) { g_spartA[c * BB + b] = r1[0]; g_spartB[c * BB + b] = r2[0]; }
}

__global__ void k_fin() {
    int b = threadIdx.x;
    if (b >= BB) return;
    float s = 0.f, s2 = 0.f;
    for (int c = 0; c < SCH; c++) { s += g_spartA[c * BB + b]; s2 += g_spartB[c * BB + b]; }
    const float inv = 1.0f / (float)(NN * DI);
    float m = s * inv;
    float v = s2 * inv - m * m;
    g_mean[b] = m;
    g_rstd[b] = rsqrtf(v + LN_EPS);
}

// ---------------- slots = mu + exp(logsigma) * slots_init ---------------
__global__ void k_sinit(const float* __restrict__ si, const float* __restrict__ mu,
                        const float* __restrict__ ls) {
    int i = blockIdx.x * 256 + threadIdx.x;
    int d = i & (DO - 1);
    g_slots[i] = mu[d] + expf(ls[d]) * si[i];
}

// ---------------- Wqk = qW^T @ kW  (grid: 64 blocks) --------------------
__global__ void __launch_bounds__(256) k_wqk(const float* __restrict__ qW,
                                             const float* __restrict__ qb,
                                             const float* __restrict__ kW,
                                             const float* __restrict__ kb, int t) {
    int d0 = blockIdx.x * 4, i = threadIdx.x;
    int wid = i >> 5, lane = i & 31;
    __shared__ float qcols[DO * 4];
    __shared__ float kb_s[DO], qb_s[DO];
    {
        float4 v = *(const float4*)(qW + (size_t)t * DO * DO + (size_t)i * DO + d0);
        qcols[i * 4 + 0] = v.x; qcols[i * 4 + 1] = v.y;
        qcols[i * 4 + 2] = v.z; qcols[i * 4 + 3] = v.w;
        kb_s[i] = kb[t * DO + i];
        qb_s[i] = qb[t * DO + i];
    }
    __syncthreads();
    const float* kWt = kW + (size_t)t * DO * DI;
    float acc0 = 0.f, acc1 = 0.f, acc2 = 0.f, acc3 = 0.f, accq = 0.f;
    for (int e = 0; e < DO; e++) {
        float kv = kWt[(size_t)e * DI + i];
        acc0 += qcols[e * 4 + 0] * kv;
        acc1 += qcols[e * 4 + 1] * kv;
        acc2 += qcols[e * 4 + 2] * kv;
        acc3 += qcols[e * 4 + 3] * kv;
        accq += qb_s[e] * kv;
    }
    g_Wqk[(d0 + 0) * DI + i] = acc0;
    g_Wqk[(d0 + 1) * DI + i] = acc1;
    g_Wqk[(d0 + 2) * DI + i] = acc2;
    g_Wqk[(d0 + 3) * DI + i] = acc3;
    if (blockIdx.x == 0) g_wqb[i] = accq;
    // g_wb: warps 0..3 each handle one d (warp-parallel reduction)
    if (wid < 4) {
        float s = 0.f;
        for (int e = lane; e < DO; e += 32) s += qcols[e * 4 + wid] * kb_s[e];
#pragma unroll
        for (int o = 16; o > 0; o >>= 1) s += __shfl_xor_sync(0xffffffffu, s, o);
        if (lane == 0) g_wb[d0 + wid] = s;
    }
    if (blockIdx.x == 0 && wid == 4) {
        float s = 0.f;
        for (int e = lane; e < DO; e += 32) s += qb_s[e] * kb_s[e];
#pragma unroll
        for (int o = 16; o > 0; o >>= 1) s += __shfl_xor_sync(0xffffffffu, s, o);
        if (lane == 0) g_c0[0] = s;
    }
}

// ---------------- LN1(slots) -> qk = sn @ Wqk + wqb  (grid: BB x 2) -----
__global__ void __launch_bounds__(256) k_qk(const float* __restrict__ ln1w,
                                            const float* __restrict__ ln1b) {
    int b = blockIdx.x, kh = blockIdx.y, tid = threadIdx.x;
    int wid = tid >> 5, lane = tid & 31;
    __shared__ float sl[KS * DO];
    __shared__ float ss[8 * DO];
    __shared__ float r1[256], r2[256];
    float s = 0.f, s2 = 0.f;
    for (int i = tid; i < KS * DO; i += 256) {
        float v = g_slots[b * KS * DO + i];
        sl[i] = v; s += v; s2 += v * v;
    }
    r1[tid] = s; r2[tid] = s2; __syncthreads();
    for (int o = 128; o > 0; o >>= 1) {
        if (tid < o) { r1[tid] += r1[tid + o]; r2[tid] += r2[tid + o]; }
        __syncthreads();
    }
    const float invC = 1.0f / (float)(KS * DO);
    float m = r1[0] * invC;
    float rs = rsqrtf(r2[0] * invC - m * m + LN_EPS);
    for (int i = tid; i < 8 * DO; i += 256) {
        int gi = kh * 8 * DO + i;
        ss[i] = (sl[gi] - m) * rs * ln1w[gi] + ln1b[gi];
    }
    __syncthreads();

    const float isc = 1.0f / (float)KS;
    float acc[8] = {0.f, 0.f, 0.f, 0.f, 0.f, 0.f, 0.f, 0.f};
    for (int d = 0; d < DO; d++) {
        float wv = g_Wqk[d * DI + tid];
#pragma unroll
        for (int k = 0; k < 8; k++) acc[k] += ss[k * DO + d] * wv;
    }
    float wqbv = g_wqb[tid];
#pragma unroll
    for (int k = 0; k < 8; k++)
        g_qk[b * KS * DI + (kh * 8 + k) * DI + tid] = (acc[k] + wqbv) * isc;
    // qkb: warp w handles slot w (warp-parallel)
    {
        float sb = 0.f;
        for (int d = lane; d < DO; d += 32) sb += ss[wid * DO + d] * g_wb[d];
#pragma unroll
        for (int o = 16; o > 0; o >>= 1) sb += __shfl_xor_sync(0xffffffffu, sb, o);
        if (lane == 0) g_qkb[b * KS + kh * 8 + wid] = (sb + g_c0[0]) * isc;
    }
}

// ---------------- big fused attention pass  (grid: BB x NCH) ------------
// 128 n-rows per block, 8 inner 16-row tiles. f32x2 packed FMA throughout.
__global__ void __launch_bounds__(256, 2) k_attn(const float* __restrict__ in,
                                                 const float* __restrict__ ln0w,
                                                 const float* __restrict__ ln0b) {
    int b = blockIdx.x, ch = blockIdx.y, tid = threadIdx.x;
    int kk = tid & 15, dg = tid >> 4;
    int wid = tid >> 5, lane = tid & 31;

    __shared__ float4 xs[16 * 64];       // 16 rows x 256 floats
    __shared__ float  dist[KS][17];
    __shared__ float  attn[KS][17];
    __shared__ float  red[8][16 * 17];
    __shared__ float  qkb_s[KS];

    // qk segment for (kk, dg): 16 floats as 8 float2 (already /KS scaled)
    const float2* qp = (const float2*)(g_qk + ((size_t)b * KS + kk) * DI + dg * 16);
    float2 q[8];
#pragma unroll
    for (int j = 0; j < 8; j++) q[j] = qp[j];
    if (tid < KS) qkb_s[tid] = g_qkb[b * KS + tid];
    float mean = g_mean[b], rstd = g_rstd[b];

    float2 u[8];
#pragma unroll
    for (int j = 0; j < 8; j++) u[j] = make_float2(0.f, 0.f);
    float Sa = 0.f;
    __syncthreads();

    for (int g = 0; g < 8; g++) {
        int n0 = ch * 128 + g * 16;
        const float4* xin = (const float4*)(in + ((size_t)b * NN + n0) * DI);
        const float4* wv4 = (const float4*)(ln0w + (size_t)n0 * DI);
        const float4* bv4 = (const float4*)(ln0b + (size_t)n0 * DI);
        for (int i = tid; i < 1024; i += 256) {
            float4 v = xin[i], w = wv4[i], bb = bv4[i];
            float4 o;
            o.x = (v.x - mean) * rstd * w.x + bb.x;
            o.y = (v.y - mean) * rstd * w.y + bb.y;
            o.z = (v.z - mean) * rstd * w.z + bb.z;
            o.w = (v.w - mean) * rstd * w.w + bb.w;
            xs[i] = o;
        }
        __syncthreads();

        // phase1: packed partial dots over this thread's 16-d segment
        float p[16];
#pragma unroll
        for (int n = 0; n < 16; n++) {
            const float2* xr = (const float2*)&xs[n * 64 + dg * 4];
            float2 acc = make_float2(0.f, 0.f);
#pragma unroll
            for (int j = 0; j < 8; j++) ffma2(acc, q[j], xr[j]);
            p[n] = acc.x + acc.y;
        }
#pragma unroll
        for (int n = 0; n < 16; n++)
            p[n] += __shfl_xor_sync(0xffffffffu, p[n], 16);
        if (lane < 16) {
#pragma unroll
            for (int n = 0; n < 16; n++) red[wid][lane * 17 + n] = p[n];
        }
        __syncthreads();

        // reduce 8 warps -> dist
        {
            int rkk = tid & 15, rn = tid >> 4;
            float s = 0.f;
#pragma unroll
            for (int w = 0; w < 8; w++) s += red[w][rkk * 17 + rn];
            dist[rkk][rn] = s + qkb_s[rkk];
        }
        __syncthreads();

        // softmax over slot dim: 32 lanes, n = lane&15, k-half = lane>>4
        if (tid < 32) {
            int n = lane & 15, h = lane >> 4;
            float mx = -1e30f;
#pragma unroll
            for (int j = 0; j < 8; j++) mx = fmaxf(mx, dist[h * 8 + j][n]);
            mx = fmaxf(mx, __shfl_xor_sync(0xffffffffu, mx, 16));
            float e[8]; float sm = 0.f;
#pragma unroll
            for (int j = 0; j < 8; j++) {
                e[j] = __expf(dist[h * 8 + j][n] - mx);
                sm += e[j];
            }
            sm += __shfl_xor_sync(0xffffffffu, sm, 16);
            float iv = 1.0f / sm;
#pragma unroll
            for (int j = 0; j < 8; j++) attn[h * 8 + j][n] = e[j] * iv;
        }
        __syncthreads();

        if (tid < 16) {
#pragma unroll
            for (int n = 0; n < 16; n++) Sa += attn[tid][n];
        }

        // phase2: packed u accumulation (x reads are 2-address broadcasts)
#pragma unroll
        for (int n = 0; n < 16; n++) {
            float w = attn[kk][n];
            float2 w2 = make_float2(w, w);
            const float2* xr = (const float2*)&xs[n * 64 + dg * 4];
#pragma unroll
            for (int j = 0; j < 8; j++) ffma2(u[j], w2, xr[j]);
        }
        __syncthreads();
    }

    float4* up = (float4*)(g_upart + (((size_t)ch * BB + b) * KS + kk) * DI + dg * 16);
    up[0] = make_float4(u[0].x, u[0].y, u[1].x, u[1].y);
    up[1] = make_float4(u[2].x, u[2].y, u[3].x, u[3].y);
    up[2] = make_float4(u[4].x, u[4].y, u[5].x, u[5].y);
    up[3] = make_float4(u[6].x, u[6].y, u[7].x, u[7].y);
    if (tid < 16) g_Spart[(ch * BB + b) * KS + tid] = Sa;
}

// ---------------- reduce partials, V proj  (grid: BB x 2) ---------------
__global__ void __launch_bounds__(256) k_vproj(const float* __restrict__ vb, int t) {
    int b = blockIdx.x, kh = blockIdx.y, tid = threadIdx.x;
    __shared__ float wxs[8 * DI];
    __shared__ float wss[8], ivs[8];
    if (tid < 8) {
        float S = 0.f;
        for (int c = 0; c < NCH; c++) S += g_Spart[(c * BB + b) * KS + kh * 8 + tid];
        float iv = 1.0f / (S + 1e-7f);
        ivs[tid] = iv; wss[tid] = S * iv;
    }
    __syncthreads();
    for (int ii = tid; ii < 512; ii += 256) {
        int k = ii >> 6;
        const float4* src = (const float4*)g_upart +
            (((size_t)b * KS) + kh * 8 + k) * (DI / 4) + (ii & 63);
        float4 s = make_float4(0.f, 0.f, 0.f, 0.f);
#pragma unroll 8
        for (int c = 0; c < NCH; c++) {
            float4 v = src[(size_t)c * (BB * KS * DI / 4)];
            s.x += v.x; s.y += v.y; s.z += v.z; s.w += v.w;
        }
        float iv = ivs[k];
        s.x *= iv; s.y *= iv; s.z *= iv; s.w *= iv;
        ((float4*)wxs)[ii] = s;
    }
    __syncthreads();
    const float* vt = g_vWt + (size_t)t * DI * DO;
    float acc[8] = {0.f, 0.f, 0.f, 0.f, 0.f, 0.f, 0.f, 0.f};
    for (int d = 0; d < DI; d++) {
        float wv = vt[(size_t)d * DO + tid];
#pragma unroll
        for (int k = 0; k < 8; k++) acc[k] += wxs[k * DI + d] * wv;
    }
    float vbv = vb[t * DO + tid];
#pragma unroll
    for (int k = 0; k < 8; k++)
        g_spre[b * KS * DO + (kh * 8 + k) * DO + tid] = acc[k] + vbv * wss[k];
}

// ---------------- LN2 + MLP + residual ----------------------------------
__global__ void __launch_bounds__(256) k_mlp(const float* __restrict__ ln2w,
                                             const float* __restrict__ ln2b,
                                             const float* __restrict__ m1b,
                                             const float* __restrict__ m2b,
                                             int t, float* __restrict__ out) {
    int b = blockIdx.x, kq = blockIdx.y, tid = threadIdx.x;
    __shared__ float h0[4 * DO];
    __shared__ float hh[4 * HI];
    __shared__ float r1[256], r2[256];
    float s = 0.f, s2 = 0.f;
    for (int i = tid; i < KS * DO; i += 256) {
        float v = g_spre[b * KS * DO + i];
        s += v; s2 += v * v;
    }
    r1[tid] = s; r2[tid] = s2; __syncthreads();
    for (int o = 128; o > 0; o >>= 1) {
        if (tid < o) { r1[tid] += r1[tid + o]; r2[tid] += r2[tid + o]; }
        __syncthreads();
    }
    const float invC = 1.0f / (float)(KS * DO);
    float m = r1[0] * invC;
    float rs = rsqrtf(r2[0] * invC - m * m + LN_EPS);
    for (int i = tid; i < 4 * DO; i += 256) {
        int gi = kq * 4 * DO + i;
        float v = g_spre[b * KS * DO + gi];
        h0[i] = (v - m) * rs * ln2w[gi] + ln2b[gi];
    }
    __syncthreads();

    const float* w1 = g_m1Wt + (size_t)t * DO * HI;
    {
        float a0[4] = {0.f, 0.f, 0.f, 0.f}, a1[4] = {0.f, 0.f, 0.f, 0.f};
        for (int d = 0; d < DO; d++) {
            float wA = w1[(size_t)d * HI + tid];
            float wB = w1[(size_t)d * HI + tid + 256];
#pragma unroll
            for (int k = 0; k < 4; k++) {
                float hv = h0[k * DO + d];
                a0[k] += hv * wA; a1[k] += hv * wB;
            }
        }
        float bA = m1b[t * HI + tid], bB = m1b[t * HI + tid + 256];
#pragma unroll
        for (int k = 0; k < 4; k++) {
            hh[k * HI + tid]       = fmaxf(a0[k] + bA, 0.f);
            hh[k * HI + tid + 256] = fmaxf(a1[k] + bB, 0.f);
        }
    }
    __syncthreads();

    const float* w2 = g_m2Wt + (size_t)t * HI * DO;
    float a[4] = {0.f, 0.f, 0.f, 0.f};
    for (int h = 0; h < HI; h++) {
        float wv = w2[(size_t)h * DO + tid];
#pragma unroll
        for (int k = 0; k < 4; k++) a[k] += hh[k * HI + h] * wv;
    }
    float b2 = m2b[t * DO + tid];
#pragma unroll
    for (int k = 0; k < 4; k++) {
        int gi = (kq * 4 + k) * DO + tid;
        float val = g_spre[b * KS * DO + gi] + a[k] + b2;
        g_slots[b * KS * DO + gi] = val;
        if (out) out[(size_t)b * KS * DO + gi] = val;
    }
}

// ---------------- host launcher -----------------------------------------
extern "C" void kernel_launch(void* const* d_in, const int* in_sizes, int n_in,
                              void* d_out, int out_size) {
    const float* inputs     = (const float*)d_in[0];
    const float* slots_init = (const float*)d_in[1];
    const float* mu         = (const float*)d_in[2];
    const float* logsigma   = (const float*)d_in[3];
    const float* ln0w       = (const float*)d_in[4];
    const float* ln0b       = (const float*)d_in[5];
    const float* ln1w       = (const float*)d_in[6];
    const float* ln1b       = (const float*)d_in[7];
    const float* ln2w       = (const float*)d_in[8];
    const float* ln2b       = (const float*)d_in[9];
    const float* qW         = (const float*)d_in[10];
    const float* qb         = (const float*)d_in[11];
    const float* kW         = (const float*)d_in[12];
    const float* kb         = (const float*)d_in[13];
    const float* vW         = (const float*)d_in[14];
    const float* vb         = (const float*)d_in[15];
    const float* m1W        = (const float*)d_in[16];
    const float* m1b        = (const float*)d_in[17];
    const float* m2W        = (const float*)d_in[18];
    const float* m2b        = (const float*)d_in[19];
    float* out = (float*)d_out;

    float* vWt;  cudaGetSymbolAddress((void**)&vWt,  g_vWt);
    float* m1Wt; cudaGetSymbolAddress((void**)&m1Wt, g_m1Wt);
    float* m2Wt; cudaGetSymbolAddress((void**)&m2Wt, g_m2Wt);
    k_tr<<<dim3(DI / 32, DO / 32, TT), 256>>>(vW, vWt, DO, DI);
    k_tr<<<dim3(DO / 32, HI / 32, TT), 256>>>(m1W, m1Wt, HI, DO);
    k_tr<<<dim3(HI / 32, DO / 32, TT), 256>>>(m2W, m2Wt, DO, HI);

    k_stats<<<dim3(BB, SCH), 256>>>(inputs);
    k_fin<<<1, BB>>>();
    k_sinit<<<(BB * KS * DO) / 256, 256>>>(slots_init, mu, logsigma);

    for (int t = 0; t < TT; t++) {
        k_wqk<<<64, 256>>>(qW, qb, kW, kb, t);
        k_qk<<<dim3(BB, 2), 256>>>(ln1w, ln1b);
        k_attn<<<dim3(BB, NCH), 256>>>(inputs, ln0w, ln0b);
        k_vproj<<<dim3(BB, 2), 256>>>(vb, t);
        k_mlp<<<dim3(BB, 4), 256>>>(ln2w, ln2b, m1b, m2b, t,
                                    (t == TT - 1) ? out : (float*)nullptr);
    }
}